// round 1
// baseline (speedup 1.0000x reference)
#include <cuda_runtime.h>
#include <math.h>

#define IMG   512
#define PIX   (IMG * IMG)
#define NIMG  64
#define TX    256
#define RPB   64
#define NITER (RPB + 10)            // 74 streamed rows per block
#define NOUTER 7                    // 7*11 = 77 >= NITER
#define PADW  (TX + 12)
#define GX    (IMG / TX)            // 2
#define GY    (IMG / RPB)           // 8
#define GZ    (NIMG / 2)            // 32 image pairs (f32x2 packing)
#define NBLK  (GX * GY * GZ)        // 512

typedef unsigned long long u64;

__device__ double g_part[NBLK];

static __device__ __forceinline__ u64 pk2(float a, float b) {
    u64 r; asm("mov.b64 %0, {%1, %2};" : "=l"(r) : "f"(a), "f"(b)); return r;
}
static __device__ __forceinline__ void unpk2(u64 v, float& a, float& b) {
    asm("mov.b64 {%0, %1}, %2;" : "=f"(a), "=f"(b) : "l"(v));
}
static __device__ __forceinline__ u64 f2add(u64 a, u64 b) {
    u64 d; asm("add.rn.f32x2 %0, %1, %2;" : "=l"(d) : "l"(a), "l"(b)); return d;
}
static __device__ __forceinline__ u64 f2mul(u64 a, u64 b) {
    u64 d; asm("mul.rn.f32x2 %0, %1, %2;" : "=l"(d) : "l"(a), "l"(b)); return d;
}
static __device__ __forceinline__ u64 f2fma(u64 a, u64 b, u64 c) {
    u64 d; asm("fma.rn.f32x2 %0, %1, %2, %3;" : "=l"(d) : "l"(a), "l"(b), "l"(c)); return d;
}

__global__ void __launch_bounds__(TX, 1) ssim_main(
    const float* __restrict__ pred, const float* __restrict__ gt)
{
    __shared__ float2 sp[2][PADW];
    __shared__ float2 sg[2][PADW];
    __shared__ float wred[TX / 32];

    const int tid = threadIdx.x;
    const int cx  = blockIdx.x * TX;
    const int ry0 = blockIdx.y * RPB;
    const int im0 = blockIdx.z;
    const int im1 = im0 + (NIMG / 2);

    const float* p0 = pred + (size_t)im0 * PIX;
    const float* p1 = pred + (size_t)im1 * PIX;
    const float* g0 = gt   + (size_t)im0 * PIX;
    const float* g1 = gt   + (size_t)im1 * PIX;

    // Gaussian 1D weights (matches reference: sigma = 11/6, zero-padded conv)
    float w[6];
    {
        const float sig = 11.0f / 6.0f;
        const float inv = 1.0f / (2.0f * sig * sig);
        float e[6];
        #pragma unroll
        for (int d = 0; d < 6; ++d) e[d] = expf(-(float)(d * d) * inv);
        float s = e[0] + 2.f * (e[1] + e[2] + e[3] + e[4] + e[5]);
        #pragma unroll
        for (int d = 0; d < 6; ++d) w[d] = e[d] / s;
    }
    u64 w2[6];
    #pragma unroll
    for (int d = 0; d < 6; ++d) w2[d] = pk2(w[d], w[d]);

    const float C1 = 0.01f * 0.01f;
    const float C2 = 0.03f * 0.03f;
    const u64 c1_2  = pk2(C1, C1);
    const u64 c2_2  = pk2(C2, C2);
    const u64 c21_2 = pk2(C1 + C2, C1 + C2);
    const u64 two2  = pk2(2.f, 2.f);
    const u64 n2_2  = pk2(-2.f, -2.f);
    const u64 n1_2  = pk2(-1.f, -1.f);

    // 11-row ring buffers of horizontally-blurred channels (registers)
    u64 rP[11], rG[11], rPP[11], rGG[11], rPG[11];
    u64 acc = pk2(0.f, 0.f);

    const int cmain = cx + tid - 5;
    const int chalo = cx + TX + tid - 5;

    float pm0, pm1, gm0, gm1;   // prefetched main column
    float ph0, ph1, gh0, gh1;   // prefetched halo column (tid < 10)

    // prefetch first row (t = 0)
    {
        const int yin = ry0 - 5;
        const bool rok = ((unsigned)yin < IMG);
        const bool ok  = rok && ((unsigned)cmain < IMG);
        const size_t off = (size_t)yin * IMG + cmain;
        pm0 = ok ? p0[off] : 0.f;  pm1 = ok ? p1[off] : 0.f;
        gm0 = ok ? g0[off] : 0.f;  gm1 = ok ? g1[off] : 0.f;
        ph0 = ph1 = gh0 = gh1 = 0.f;
        if (tid < 10) {
            const bool ok2 = rok && ((unsigned)chalo < IMG);
            const size_t off2 = (size_t)yin * IMG + chalo;
            ph0 = ok2 ? p0[off2] : 0.f;  ph1 = ok2 ? p1[off2] : 0.f;
            gh0 = ok2 ? g0[off2] : 0.f;  gh1 = ok2 ? g1[off2] : 0.f;
        }
    }

    for (int outer = 0; outer < NOUTER; ++outer) {
        #pragma unroll
        for (int k = 0; k < 11; ++k) {
            const int t = outer * 11 + k;
            if (t < NITER) {
                float2* bp = sp[t & 1];
                float2* bg = sg[t & 1];
                bp[tid] = make_float2(pm0, pm1);
                bg[tid] = make_float2(gm0, gm1);
                if (tid < 10) {
                    bp[TX + tid] = make_float2(ph0, ph1);
                    bg[TX + tid] = make_float2(gh0, gh1);
                }
            }
            __syncthreads();
            if (t + 1 < NITER) {
                // software prefetch next row (hides LDG latency behind compute)
                const int yin = ry0 - 5 + t + 1;
                const bool rok = ((unsigned)yin < IMG);
                const bool ok  = rok && ((unsigned)cmain < IMG);
                const size_t off = (size_t)yin * IMG + cmain;
                pm0 = ok ? p0[off] : 0.f;  pm1 = ok ? p1[off] : 0.f;
                gm0 = ok ? g0[off] : 0.f;  gm1 = ok ? g1[off] : 0.f;
                if (tid < 10) {
                    const bool ok2 = rok && ((unsigned)chalo < IMG);
                    const size_t off2 = (size_t)yin * IMG + chalo;
                    ph0 = ok2 ? p0[off2] : 0.f;  ph1 = ok2 ? p1[off2] : 0.f;
                    gh0 = ok2 ? g0[off2] : 0.f;  gh1 = ok2 ? g1[off2] : 0.f;
                }
            }
            if (t < NITER) {
                // ---- horizontal blur of 5 channels (symmetric taps) ----
                const u64* P = (const u64*)&sp[t & 1][tid];
                const u64* G = (const u64*)&sg[t & 1][tid];
                u64 pc = P[5], gc = G[5];
                u64 hP  = f2mul(pc, w2[0]);
                u64 hG  = f2mul(gc, w2[0]);
                u64 hPP = f2mul(f2mul(pc, pc), w2[0]);
                u64 hGG = f2mul(f2mul(gc, gc), w2[0]);
                u64 hPG = f2mul(f2mul(pc, gc), w2[0]);
                #pragma unroll
                for (int d = 1; d <= 5; ++d) {
                    u64 pl = P[5 - d], pr = P[5 + d];
                    u64 gl = G[5 - d], gr = G[5 + d];
                    hP  = f2fma(f2add(pl, pr), w2[d], hP);
                    hG  = f2fma(f2add(gl, gr), w2[d], hG);
                    hPP = f2fma(f2fma(pr, pr, f2mul(pl, pl)), w2[d], hPP);
                    hGG = f2fma(f2fma(gr, gr, f2mul(gl, gl)), w2[d], hGG);
                    hPG = f2fma(f2fma(pr, gr, f2mul(pl, gl)), w2[d], hPG);
                }
                rP[k] = hP; rG[k] = hG; rPP[k] = hPP; rGG[k] = hGG; rPG[k] = hPG;

                if (t >= 10) {
                    // ---- vertical blur (ring slots constant-folded via unroll) ----
                    u64 m1, m2, s11, s22, s12;
                    #define VS(j) (((k) + 6 + (j)) % 11)
                    #define VBLUR(dst, r)                                         \
                        { u64 m = f2mul(r[VS(0)], w2[0]);                         \
                          m = f2fma(f2add(r[VS(-1)], r[VS(1)]), w2[1], m);        \
                          m = f2fma(f2add(r[VS(-2)], r[VS(2)]), w2[2], m);        \
                          m = f2fma(f2add(r[VS(-3)], r[VS(3)]), w2[3], m);        \
                          m = f2fma(f2add(r[VS(-4)], r[VS(4)]), w2[4], m);        \
                          m = f2fma(f2add(r[VS(-5)], r[VS(5)]), w2[5], m);        \
                          dst = m; }
                    VBLUR(m1,  rP);
                    VBLUR(m2,  rG);
                    VBLUR(s11, rPP);
                    VBLUR(s22, rGG);
                    VBLUR(s12, rPG);
                    #undef VBLUR
                    #undef VS

                    // ---- SSIM map value ----
                    u64 m12 = f2mul(m1, m2);
                    u64 A  = f2fma(m12, two2, c1_2);                         // 2*mu1*mu2 + C1
                    u64 B  = f2fma(s12, two2, f2fma(m12, n2_2, c2_2));       // 2*sigma12 + C2
                    u64 Cq = f2fma(m2, m2, f2fma(m1, m1, c1_2));             // mu1^2+mu2^2+C1
                    u64 Dq = f2fma(Cq, n1_2, f2add(f2add(s11, s22), c21_2)); // sigma1+sigma2+C2
                    u64 num = f2mul(A, B);
                    u64 den = f2mul(Cq, Dq);
                    float na, nb, da, db;
                    unpk2(num, na, nb); unpk2(den, da, db);
                    const float qa = __fdividef(na, da);
                    const float qb = __fdividef(nb, db);
                    acc = f2add(acc, pk2(qa, qb));
                }
            }
        }
    }

    // ---- block reduction (deterministic partials, no atomics) ----
    float a0, a1; unpk2(acc, a0, a1);
    float s = a0 + a1;
    #pragma unroll
    for (int o = 16; o > 0; o >>= 1) s += __shfl_xor_sync(0xffffffffu, s, o);
    if ((tid & 31) == 0) wred[tid >> 5] = s;
    __syncthreads();
    if (tid == 0) {
        double bs = 0.0;
        #pragma unroll
        for (int i = 0; i < TX / 32; ++i) bs += (double)wred[i];
        const int bid = blockIdx.x + GX * (blockIdx.y + GY * blockIdx.z);
        g_part[bid] = bs;
    }
}

__global__ void ssim_finalize(float* __restrict__ out)
{
    __shared__ double sh[NBLK];
    const int tid = threadIdx.x;
    sh[tid] = g_part[tid];
    __syncthreads();
    #pragma unroll
    for (int s = NBLK / 2; s > 0; s >>= 1) {
        if (tid < s) sh[tid] += sh[tid + s];
        __syncthreads();
    }
    if (tid == 0)
        out[0] = (float)(1.0 - sh[0] / ((double)NIMG * (double)PIX));
}

extern "C" void kernel_launch(void* const* d_in, const int* in_sizes, int n_in,
                              void* d_out, int out_size)
{
    const float* pred = (const float*)d_in[0];
    const float* gt   = (const float*)d_in[1];
    float* out = (float*)d_out;

    dim3 grid(GX, GY, GZ);
    ssim_main<<<grid, TX>>>(pred, gt);
    ssim_finalize<<<1, NBLK>>>(out);
}

// round 2
// speedup vs baseline: 1.5797x; 1.5797x over previous
#include <cuda_runtime.h>
#include <math.h>

#define IMG   512
#define PIX   (IMG * IMG)
#define NIMG  64
#define TX    128
#define RPB   64
#define NITER (RPB + 10)            // 74 streamed rows per block
#define NOUTER 7                    // 7*11 = 77 >= NITER
#define PADW  (TX + 12)
#define GX    (IMG / TX)            // 4
#define GY    (IMG / RPB)           // 8
#define GZ    (NIMG / 2)            // 32 image pairs (f32x2 packing)
#define NBLK  (GX * GY * GZ)        // 1024

typedef unsigned long long u64;

__device__ double g_part[NBLK];

static __device__ __forceinline__ u64 pk2(float a, float b) {
    u64 r; asm("mov.b64 %0, {%1, %2};" : "=l"(r) : "f"(a), "f"(b)); return r;
}
static __device__ __forceinline__ void unpk2(u64 v, float& a, float& b) {
    asm("mov.b64 {%0, %1}, %2;" : "=f"(a), "=f"(b) : "l"(v));
}
static __device__ __forceinline__ u64 f2add(u64 a, u64 b) {
    u64 d; asm("add.rn.f32x2 %0, %1, %2;" : "=l"(d) : "l"(a), "l"(b)); return d;
}
static __device__ __forceinline__ u64 f2mul(u64 a, u64 b) {
    u64 d; asm("mul.rn.f32x2 %0, %1, %2;" : "=l"(d) : "l"(a), "l"(b)); return d;
}
static __device__ __forceinline__ u64 f2fma(u64 a, u64 b, u64 c) {
    u64 d; asm("fma.rn.f32x2 %0, %1, %2, %3;" : "=l"(d) : "l"(a), "l"(b), "l"(c)); return d;
}

__global__ void __launch_bounds__(TX, 3) ssim_main(
    const float* __restrict__ pred, const float* __restrict__ gt)
{
    // Interleaved tile: (p_im0, p_im1, g_im0, g_im1) per column.
    __shared__ float4 sv[2][PADW];
    __shared__ float wred[TX / 32];

    const int tid = threadIdx.x;
    const int cx  = blockIdx.x * TX;
    const int ry0 = blockIdx.y * RPB;
    const int im0 = blockIdx.z;

    const float* p0 = pred + (size_t)im0 * PIX;
    const float* p1 = pred + (size_t)(im0 + NIMG / 2) * PIX;
    const float* g0 = gt   + (size_t)im0 * PIX;
    const float* g1 = gt   + (size_t)(im0 + NIMG / 2) * PIX;

    // Gaussian 1D weights (sigma = 11/6, normalized)
    float w[6];
    {
        const float sig = 11.0f / 6.0f;
        const float inv = 1.0f / (2.0f * sig * sig);
        float e[6];
        #pragma unroll
        for (int d = 0; d < 6; ++d) e[d] = expf(-(float)(d * d) * inv);
        float s = e[0] + 2.f * (e[1] + e[2] + e[3] + e[4] + e[5]);
        #pragma unroll
        for (int d = 0; d < 6; ++d) w[d] = e[d] / s;
    }
    u64 w2[6];
    #pragma unroll
    for (int d = 0; d < 6; ++d) w2[d] = pk2(w[d], w[d]);

    const float C1 = 0.01f * 0.01f;
    const float C2 = 0.03f * 0.03f;
    const u64 c1_2  = pk2(C1, C1);
    const u64 c2_2  = pk2(C2, C2);
    const u64 c12_2 = pk2(C1 + C2, C1 + C2);
    const u64 two2  = pk2(2.f, 2.f);
    const u64 n2_2  = pk2(-2.f, -2.f);
    const u64 n1_2  = pk2(-1.f, -1.f);

    // 11-row ring buffers of horizontally-blurred channels (registers):
    // P = mu-blur(pred), G = mu-blur(gt), S = blur(p^2+g^2), X = blur(p*g)
    u64 rP[11], rG[11], rS[11], rX[11];
    u64 acc = pk2(0.f, 0.f);

    const int cmain = cx + tid - 5;
    const int chalo = cx + TX + tid - 5;

    float pm0, pm1, gm0, gm1;   // prefetched main column
    float ph0, ph1, gh0, gh1;   // prefetched halo column (tid < 10)

    // prefetch first row (t = 0)
    {
        const int yin = ry0 - 5;
        const bool rok = ((unsigned)yin < IMG);
        const bool ok  = rok && ((unsigned)cmain < IMG);
        const int off = yin * IMG + cmain;
        pm0 = ok ? p0[off] : 0.f;  pm1 = ok ? p1[off] : 0.f;
        gm0 = ok ? g0[off] : 0.f;  gm1 = ok ? g1[off] : 0.f;
        ph0 = ph1 = gh0 = gh1 = 0.f;
        if (tid < 10) {
            const bool ok2 = rok && ((unsigned)chalo < IMG);
            const int off2 = yin * IMG + chalo;
            ph0 = ok2 ? p0[off2] : 0.f;  ph1 = ok2 ? p1[off2] : 0.f;
            gh0 = ok2 ? g0[off2] : 0.f;  gh1 = ok2 ? g1[off2] : 0.f;
        }
    }

    for (int outer = 0; outer < NOUTER; ++outer) {
        #pragma unroll
        for (int k = 0; k < 11; ++k) {
            const int t = outer * 11 + k;
            if (t < NITER) {
                float4* bv = sv[t & 1];
                bv[tid] = make_float4(pm0, pm1, gm0, gm1);
                if (tid < 10)
                    bv[TX + tid] = make_float4(ph0, ph1, gh0, gh1);
            }
            __syncthreads();
            if (t + 1 < NITER) {
                // software prefetch next row (hides LDG latency behind compute)
                const int yin = ry0 - 5 + t + 1;
                const bool rok = ((unsigned)yin < IMG);
                const bool ok  = rok && ((unsigned)cmain < IMG);
                const int off = yin * IMG + cmain;
                pm0 = ok ? p0[off] : 0.f;  pm1 = ok ? p1[off] : 0.f;
                gm0 = ok ? g0[off] : 0.f;  gm1 = ok ? g1[off] : 0.f;
                if (tid < 10) {
                    const bool ok2 = rok && ((unsigned)chalo < IMG);
                    const int off2 = yin * IMG + chalo;
                    ph0 = ok2 ? p0[off2] : 0.f;  ph1 = ok2 ? p1[off2] : 0.f;
                    gh0 = ok2 ? g0[off2] : 0.f;  gh1 = ok2 ? g1[off2] : 0.f;
                }
            }
            if (t < NITER) {
                // ---- horizontal blur: 4 channels, symmetric taps ----
                const float4* V = &sv[t & 1][tid];
                float4 c = V[5];
                u64 pc = pk2(c.x, c.y), gc = pk2(c.z, c.w);
                u64 hP  = f2mul(pc, w2[0]);
                u64 hG  = f2mul(gc, w2[0]);
                u64 hS  = f2mul(f2fma(gc, gc, f2mul(pc, pc)), w2[0]);
                u64 hX  = f2mul(f2mul(pc, gc), w2[0]);
                #pragma unroll
                for (int d = 1; d <= 5; ++d) {
                    float4 L = V[5 - d], R = V[5 + d];
                    u64 pl = pk2(L.x, L.y), gl = pk2(L.z, L.w);
                    u64 pr = pk2(R.x, R.y), gr = pk2(R.z, R.w);
                    hP = f2fma(f2add(pl, pr), w2[d], hP);
                    hG = f2fma(f2add(gl, gr), w2[d], hG);
                    u64 ss = f2fma(pr, pr, f2mul(pl, pl));
                    ss = f2fma(gl, gl, ss);
                    ss = f2fma(gr, gr, ss);
                    hS = f2fma(ss, w2[d], hS);
                    hX = f2fma(f2fma(pr, gr, f2mul(pl, gl)), w2[d], hX);
                }
                rP[k] = hP; rG[k] = hG; rS[k] = hS; rX[k] = hX;

                if (t >= 10) {
                    // ---- vertical blur (ring slots constant-folded; split chains) ----
                    u64 m1, m2, sS, s12;
                    #define VS(j) (((k) + 6 + (j)) % 11)
                    #define VBLUR(dst, r)                                          \
                        { u64 pa = f2fma(f2add(r[VS(-1)], r[VS(1)]), w2[1],        \
                                         f2mul(r[VS(0)], w2[0]));                  \
                          pa = f2fma(f2add(r[VS(-3)], r[VS(3)]), w2[3], pa);       \
                          u64 pb = f2mul(f2add(r[VS(-2)], r[VS(2)]), w2[2]);       \
                          pb = f2fma(f2add(r[VS(-4)], r[VS(4)]), w2[4], pb);       \
                          pb = f2fma(f2add(r[VS(-5)], r[VS(5)]), w2[5], pb);       \
                          dst = f2add(pa, pb); }
                    VBLUR(m1,  rP);
                    VBLUR(m2,  rG);
                    VBLUR(sS,  rS);
                    VBLUR(s12, rX);
                    #undef VBLUR
                    #undef VS

                    // ---- SSIM map value ----
                    u64 m12 = f2mul(m1, m2);
                    u64 A  = f2fma(m12, two2, c1_2);                    // 2 mu1 mu2 + C1
                    u64 B  = f2fma(s12, two2, f2fma(m12, n2_2, c2_2));  // 2 sigma12 + C2
                    u64 Cq = f2fma(m2, m2, f2fma(m1, m1, c1_2));        // mu1^2+mu2^2+C1
                    u64 Dq = f2fma(Cq, n1_2, f2add(sS, c12_2));         // sig1+sig2+C2
                    u64 num = f2mul(A, B);
                    u64 den = f2mul(Cq, Dq);
                    float na, nb, da, db;
                    unpk2(num, na, nb); unpk2(den, da, db);
                    acc = f2add(acc, pk2(__fdividef(na, da), __fdividef(nb, db)));
                }
            }
        }
    }

    // ---- block reduction (deterministic partials, no atomics) ----
    float a0, a1; unpk2(acc, a0, a1);
    float s = a0 + a1;
    #pragma unroll
    for (int o = 16; o > 0; o >>= 1) s += __shfl_xor_sync(0xffffffffu, s, o);
    if ((tid & 31) == 0) wred[tid >> 5] = s;
    __syncthreads();
    if (tid == 0) {
        double bs = 0.0;
        #pragma unroll
        for (int i = 0; i < TX / 32; ++i) bs += (double)wred[i];
        const int bid = blockIdx.x + GX * (blockIdx.y + GY * blockIdx.z);
        g_part[bid] = bs;
    }
}

__global__ void __launch_bounds__(NBLK) ssim_finalize(float* __restrict__ out)
{
    __shared__ double sh[NBLK];
    const int tid = threadIdx.x;
    sh[tid] = g_part[tid];
    __syncthreads();
    #pragma unroll
    for (int s = NBLK / 2; s > 0; s >>= 1) {
        if (tid < s) sh[tid] += sh[tid + s];
        __syncthreads();
    }
    if (tid == 0)
        out[0] = (float)(1.0 - sh[0] / ((double)NIMG * (double)PIX));
}

extern "C" void kernel_launch(void* const* d_in, const int* in_sizes, int n_in,
                              void* d_out, int out_size)
{
    const float* pred = (const float*)d_in[0];
    const float* gt   = (const float*)d_in[1];
    float* out = (float*)d_out;

    dim3 grid(GX, GY, GZ);
    ssim_main<<<grid, TX>>>(pred, gt);
    ssim_finalize<<<1, NBLK>>>(out);
}